// round 6
// baseline (speedup 1.0000x reference)
#include <cuda_runtime.h>
#include <cuda_fp16.h>
#include <cstdint>

#define BDIM 8192
#define INDIM 512
#define FDIM 64
#define ODIM 512
#define KDIM (INDIM * FDIM)   // 32768
#define NKC  INDIM            // 512 K-chunks of 64
#define EPSV 1e-3f

// Static device scratch (runtime allocation forbidden)
__device__ __align__(128) __half g_Wc[(size_t)ODIM * KDIM];   // 32 MB, W[o][k], k=i*64+f
__device__ __align__(128) float  g_xT[(size_t)INDIM * BDIM];  // 16 MB, x transposed [i][b]
__device__ float  g_biaseff[ODIM];

// ---------------------------------------------------------------------------
__device__ __forceinline__ uint32_t smem_u32(const void* p) {
    uint32_t a;
    asm("{ .reg .u64 t; cvta.to.shared.u64 t, %1; cvt.u32.u64 %0, t; }"
        : "=r"(a) : "l"(p));
    return a;
}

#define LDSM4(R, addr)                                                        \
    asm volatile("ldmatrix.sync.aligned.m8n8.x4.shared.b16 "                  \
                 "{%0,%1,%2,%3}, [%4];"                                       \
                 : "=r"((R)[0]), "=r"((R)[1]), "=r"((R)[2]), "=r"((R)[3])     \
                 : "r"(addr))

#define MMA16816(C, A, B0, B1)                                                \
    asm volatile("mma.sync.aligned.m16n8k16.row.col.f32.f16.f16.f32 "         \
                 "{%0,%1,%2,%3}, {%4,%5,%6,%7}, {%8,%9}, {%0,%1,%2,%3};"      \
                 : "+f"((C)[0]), "+f"((C)[1]), "+f"((C)[2]), "+f"((C)[3])     \
                 : "r"((A)[0]), "r"((A)[1]), "r"((A)[2]), "r"((A)[3]),        \
                   "r"(B0), "r"(B1))

#define CP_ASYNC16(dst, src)                                                  \
    asm volatile("cp.async.cg.shared.global [%0], [%1], 16;"                  \
                 :: "r"(dst), "l"(src) : "memory")

#define STS128(addr, v)                                                       \
    asm volatile("st.shared.v4.b32 [%0], {%1,%2,%3,%4};"                      \
                 :: "r"(addr), "r"((v)[0]), "r"((v)[1]), "r"((v)[2]),         \
                    "r"((v)[3]) : "memory")

// ---------------------------------------------------------------------------
// prep kernels
// ---------------------------------------------------------------------------
__global__ void prep_bias_kernel(const float* __restrict__ freqs,
                                 const float* __restrict__ phases,
                                 const float* __restrict__ beta,
                                 const float* __restrict__ lamb,
                                 const float* __restrict__ bias) {
    int o = blockIdx.x * blockDim.x + threadIdx.x;
    if (o >= ODIM) return;
    float sl = 0.f;
    for (int i = 0; i < INDIM; ++i) sl += lamb[(size_t)i * ODIM + o];
    float sb = 0.f;
    for (int f = 0; f < FDIM; ++f) {
        float w = freqs[f], p = phases[f];
        float m   = expf(-0.5f * w * w) * sinf(p);
        float var = 0.5f - 0.5f * expf(-2.f * w * w) * cosf(2.f * p) - m * m;
        float s   = rsqrtf(EPSV + var);
        sb += m * s * beta[f * ODIM + o];
    }
    g_biaseff[o] = bias[o] - sl * sb;
}

__global__ void prep_xT_kernel(const float* __restrict__ x) {
    __shared__ float tile[32][33];
    int i0 = blockIdx.x * 32, b0 = blockIdx.y * 32;
    int tx = threadIdx.x, ty = threadIdx.y;
#pragma unroll
    for (int j = 0; j < 32; j += 8)
        tile[ty + j][tx] = x[(size_t)(b0 + ty + j) * INDIM + i0 + tx];
    __syncthreads();
#pragma unroll
    for (int j = 0; j < 32; j += 8)
        g_xT[(size_t)(i0 + ty + j) * BDIM + b0 + tx] = tile[tx][ty + j];
}

// W[o][i*64+f] = s_f * beta[f][o] * lamb[i][o]  as fp16, K-contiguous
__global__ void prep_wc_kernel(const float* __restrict__ freqs,
                               const float* __restrict__ phases,
                               const float* __restrict__ beta,
                               const float* __restrict__ lamb) {
    __shared__ float  sS[FDIM];
    __shared__ __half tile[64 * 64];
    const int i  = blockIdx.x;
    const int o0 = blockIdx.y * 64;
    const int t  = threadIdx.x;       // 256 threads
    if (t < FDIM) {
        float w = freqs[t], p = phases[t];
        float m   = expf(-0.5f * w * w) * sinf(p);
        float var = 0.5f - 0.5f * expf(-2.f * w * w) * cosf(2.f * p) - m * m;
        sS[t] = rsqrtf(EPSV + var);
    }
    __syncthreads();
    const int f  = t & 63;
    const int ob = t >> 6;
#pragma unroll
    for (int e = 0; e < 16; ++e) {
        int ol = ob + 4 * e;
        int o  = o0 + ol;
        float v = sS[f] * beta[f * ODIM + o] * lamb[(size_t)i * ODIM + o];
        tile[ol * 64 + f] = __float2half_rn(v);
    }
    __syncthreads();
    const uint32_t* tw = (const uint32_t*)tile;
#pragma unroll
    for (int e = 0; e < 8; ++e) {
        int w2  = t + 256 * e;
        int row = w2 >> 5, col = w2 & 31;
        ((uint32_t*)(g_Wc + (size_t)(o0 + row) * KDIM + (size_t)i * 64))[col] =
            tw[row * 32 + col];
    }
}

// ---------------------------------------------------------------------------
// fused GEMM via mma.sync: out[b,o] = sum_k sin(w_f*x[b,i]+p_f)*Wc[o][k] + be[o]
// CTA: M=128(b) x N=256(o), 256 threads = 8 warps (2M x 4N), warp tile 64x64.
// K-chunks of 64 (one i), 2-stage smem pipeline.
// Smem tiles: A[128][64] fp16, B[256][64] fp16; 128B rows, XOR swizzle:
//   byte = row*128 + (col_bytes ^ ((row&7)<<4))  -> conflict-free LDSM/STS.
// ---------------------------------------------------------------------------
#define SA0 0
#define SA1 16384
#define SB0 32768
#define SB1 65536
#define SMEM_DYN (98304 + 1024)

__global__ void __launch_bounds__(256, 1)
gemm_kernel(const float* __restrict__ freqs, const float* __restrict__ phases,
            float* __restrict__ out) {
    extern __shared__ char dynraw[];
    char* dyn = (char*)(((uintptr_t)dynraw + 1023) & ~(uintptr_t)1023);
    const uint32_t db = smem_u32(dyn);

    const int tid  = threadIdx.x;
    const int lane = tid & 31;
    const int wid  = tid >> 5;
    const int wm   = wid >> 2;   // 0..1  (64 M rows each)
    const int wn   = wid & 3;    // 0..3  (64 N cols each)
    const int m_base = blockIdx.y * 128;
    const int n_base = blockIdx.x * 256;

    // --- A-generation mapping: thread owns 8 fixed f's x 4 rows ------------
    const int fg    = tid & 7;           // f-group: f = fg*8 .. fg*8+7
    const int rbase = tid >> 3;          // rows rbase + 32*r, r=0..3
    float wreg[8], preg[8];
#pragma unroll
    for (int j = 0; j < 8; ++j) {
        wreg[j] = __ldg(freqs + fg * 8 + j);
        preg[j] = __ldg(phases + fg * 8 + j);
    }
    const uint32_t gxm = (uint32_t)(rbase & 7) << 4;   // swizzle XOR (row-const)
    const uint32_t gcol = ((uint32_t)fg * 16u) ^ gxm;  // 16B granule, pre-XORed
    const float* xsrc = g_xT + m_base + rbase;

    // --- B cp.async mapping: one o-row per thread, 8x16B -------------------
    const uint32_t cbase = (uint32_t)tid * 128u;
    const uint32_t cxm   = (uint32_t)(tid & 7) << 4;
    const __half* csrc = g_Wc + (size_t)(n_base + tid) * KDIM;

    // --- ldmatrix lane addressing ------------------------------------------
    const int arow = wm * 64 + (lane & 15);
    const uint32_t aoff = (uint32_t)arow * 128u;
    const uint32_t xmA  = (uint32_t)(arow & 7) << 4;
    const uint32_t kqa  = (uint32_t)(lane >> 4) * 16u;       // k-bytes half
    const int brow = wn * 64 + (lane & 7) + (lane >> 4) * 8;
    const uint32_t boff = (uint32_t)brow * 128u;
    const uint32_t xmB  = (uint32_t)(lane & 7) << 4;
    const uint32_t kqb  = (uint32_t)((lane >> 3) & 1) * 16u;

    float acc[4][8][4];
#pragma unroll
    for (int mi = 0; mi < 4; ++mi)
#pragma unroll
        for (int nj = 0; nj < 8; ++nj)
#pragma unroll
            for (int c = 0; c < 4; ++c) acc[mi][nj][c] = 0.f;

    // A-tile generator for chunk kc into stage base `st`
    auto gen_a = [&](int kc, uint32_t st) {
#pragma unroll
        for (int r = 0; r < 4; ++r) {
            float xv = xsrc[(size_t)kc * BDIM + 32 * r];
            uint32_t h[4];
#pragma unroll
            for (int j = 0; j < 4; ++j) {
                float t0 = fmaf(wreg[2 * j],     xv, preg[2 * j]);
                float t1 = fmaf(wreg[2 * j + 1], xv, preg[2 * j + 1]);
                t0 = fmaf(-6.2831853f, rintf(t0 * 0.15915494f), t0);
                t1 = fmaf(-6.2831853f, rintf(t1 * 0.15915494f), t1);
                __half2 hh = __floats2half2_rn(__sinf(t0), __sinf(t1));
                h[j] = *(uint32_t*)&hh;
            }
            STS128(db + st + ((uint32_t)(rbase + 32 * r)) * 128u + gcol, h);
        }
    };

    // --- prologue: stage 0 <- chunk 0 ---
    {
        const char* s = (const char*)csrc;
#pragma unroll
        for (int j = 0; j < 8; ++j)
            CP_ASYNC16(db + SB0 + cbase + (((uint32_t)(j * 16)) ^ cxm),
                       s + j * 16);
        asm volatile("cp.async.commit_group;" ::: "memory");
        gen_a(0, SA0);
    }

#pragma unroll 1
    for (int kc = 0; kc < NKC; ++kc) {
        const uint32_t sa = (kc & 1) ? SA1 : SA0;
        const uint32_t sb = (kc & 1) ? SB1 : SB0;
        const uint32_t na = (kc & 1) ? SA0 : SA1;
        const uint32_t nb = (kc & 1) ? SB0 : SB1;

        asm volatile("cp.async.wait_group 0;" ::: "memory");
        __syncthreads();

        // issue next B early (hidden behind this chunk's MMA + A-gen)
        if (kc + 1 < NKC) {
            const char* s = (const char*)(csrc + (size_t)(kc + 1) * 64);
#pragma unroll
            for (int j = 0; j < 8; ++j)
                CP_ASYNC16(db + nb + cbase + (((uint32_t)(j * 16)) ^ cxm),
                           s + j * 16);
            asm volatile("cp.async.commit_group;" ::: "memory");
        }

        // --- MMA on stage (sa, sb): 4 k16 steps ---
#pragma unroll
        for (int ks = 0; ks < 4; ++ks) {
            uint32_t a[4][4];
#pragma unroll
            for (int mi = 0; mi < 4; ++mi)
                LDSM4(a[mi], db + sa + aoff + (uint32_t)mi * 2048u +
                              (((uint32_t)(ks * 32) + kqa) ^ xmA));
            uint32_t b[4][4];
#pragma unroll
            for (int nq = 0; nq < 4; ++nq)
                LDSM4(b[nq], db + sb + boff + (uint32_t)nq * 2048u +
                              (((uint32_t)(ks * 32) + kqb) ^ xmB));
#pragma unroll
            for (int mi = 0; mi < 4; ++mi)
#pragma unroll
                for (int nj = 0; nj < 8; ++nj)
                    MMA16816(acc[mi][nj], a[mi],
                             b[nj >> 1][(nj & 1) * 2],
                             b[nj >> 1][(nj & 1) * 2 + 1]);
        }

        // --- generate next A tile (MUFU/FMA overlap tensor drain) ---
        if (kc + 1 < NKC) gen_a(kc + 1, na);
    }

    // --- epilogue: acc + bias -> out ---
#pragma unroll
    for (int mi = 0; mi < 4; ++mi) {
        int row = m_base + wm * 64 + mi * 16 + (lane >> 2);
        float* o0 = out + (size_t)row * ODIM + n_base;
        float* o1 = o0 + (size_t)8 * ODIM;
#pragma unroll
        for (int nj = 0; nj < 8; ++nj) {
            int cl = wn * 64 + nj * 8 + (lane & 3) * 2;
            float b0 = __ldg(g_biaseff + n_base + cl);
            float b1 = __ldg(g_biaseff + n_base + cl + 1);
            float2 v0 = make_float2(acc[mi][nj][0] + b0, acc[mi][nj][1] + b1);
            float2 v1 = make_float2(acc[mi][nj][2] + b0, acc[mi][nj][3] + b1);
            *(float2*)(o0 + cl) = v0;
            *(float2*)(o1 + cl) = v1;
        }
    }
}

// ---------------------------------------------------------------------------
extern "C" void kernel_launch(void* const* d_in, const int* in_sizes, int n_in,
                              void* d_out, int out_size) {
    (void)in_sizes; (void)n_in; (void)out_size;
    const float* x      = (const float*)d_in[0];
    const float* freqs  = (const float*)d_in[1];
    const float* phases = (const float*)d_in[2];
    const float* beta   = (const float*)d_in[3];
    const float* lamb   = (const float*)d_in[4];
    const float* bias   = (const float*)d_in[5];
    float* out = (float*)d_out;

    cudaFuncSetAttribute(gemm_kernel,
                         cudaFuncAttributeMaxDynamicSharedMemorySize, SMEM_DYN);

    prep_bias_kernel<<<(ODIM + 255) / 256, 256>>>(freqs, phases, beta, lamb, bias);
    prep_xT_kernel<<<dim3(INDIM / 32, BDIM / 32), dim3(32, 8)>>>(x);
    prep_wc_kernel<<<dim3(INDIM, ODIM / 64), 256>>>(freqs, phases, beta, lamb);
    gemm_kernel<<<dim3(ODIM / 256, BDIM / 128), 256, SMEM_DYN>>>(freqs, phases, out);
}

// round 7
// speedup vs baseline: 1.1191x; 1.1191x over previous
#include <cuda_runtime.h>
#include <cuda_fp16.h>
#include <cstdint>

#define BDIM 8192
#define INDIM 512
#define FDIM 64
#define ODIM 512
#define KDIM (INDIM * FDIM)   // 32768
#define NKC  INDIM            // 512 K-chunks of 64
#define EPSV 1e-3f

// Static device scratch (runtime allocation forbidden)
__device__ __align__(128) __half g_Wc[(size_t)ODIM * KDIM];   // 32 MB, W[o][k], k=i*64+f
__device__ __align__(128) float  g_xT[(size_t)INDIM * BDIM];  // 16 MB, x transposed [i][b]
__device__ float  g_biaseff[ODIM];

// ---------------------------------------------------------------------------
__device__ __forceinline__ uint32_t smem_u32(const void* p) {
    uint32_t a;
    asm("{ .reg .u64 t; cvta.to.shared.u64 t, %1; cvt.u32.u64 %0, t; }"
        : "=r"(a) : "l"(p));
    return a;
}

#define LDSM4(R, addr)                                                        \
    asm volatile("ldmatrix.sync.aligned.m8n8.x4.shared.b16 "                  \
                 "{%0,%1,%2,%3}, [%4];"                                       \
                 : "=r"((R)[0]), "=r"((R)[1]), "=r"((R)[2]), "=r"((R)[3])     \
                 : "r"(addr))

#define MMA16816(C, A, B0, B1)                                                \
    asm volatile("mma.sync.aligned.m16n8k16.row.col.f32.f16.f16.f32 "         \
                 "{%0,%1,%2,%3}, {%4,%5,%6,%7}, {%8,%9}, {%0,%1,%2,%3};"      \
                 : "+f"((C)[0]), "+f"((C)[1]), "+f"((C)[2]), "+f"((C)[3])     \
                 : "r"((A)[0]), "r"((A)[1]), "r"((A)[2]), "r"((A)[3]),        \
                   "r"(B0), "r"(B1))

#define CP_ASYNC16(dst, src)                                                  \
    asm volatile("cp.async.cg.shared.global [%0], [%1], 16;"                  \
                 :: "r"(dst), "l"(src) : "memory")

#define STS128(addr, v)                                                       \
    asm volatile("st.shared.v4.b32 [%0], {%1,%2,%3,%4};"                      \
                 :: "r"(addr), "r"((v)[0]), "r"((v)[1]), "r"((v)[2]),         \
                    "r"((v)[3]) : "memory")

// ---------------------------------------------------------------------------
// prep kernels (unchanged from passing R6)
// ---------------------------------------------------------------------------
__global__ void prep_bias_kernel(const float* __restrict__ freqs,
                                 const float* __restrict__ phases,
                                 const float* __restrict__ beta,
                                 const float* __restrict__ lamb,
                                 const float* __restrict__ bias) {
    int o = blockIdx.x * blockDim.x + threadIdx.x;
    if (o >= ODIM) return;
    float sl = 0.f;
    for (int i = 0; i < INDIM; ++i) sl += lamb[(size_t)i * ODIM + o];
    float sb = 0.f;
    for (int f = 0; f < FDIM; ++f) {
        float w = freqs[f], p = phases[f];
        float m   = expf(-0.5f * w * w) * sinf(p);
        float var = 0.5f - 0.5f * expf(-2.f * w * w) * cosf(2.f * p) - m * m;
        float s   = rsqrtf(EPSV + var);
        sb += m * s * beta[f * ODIM + o];
    }
    g_biaseff[o] = bias[o] - sl * sb;
}

__global__ void prep_xT_kernel(const float* __restrict__ x) {
    __shared__ float tile[32][33];
    int i0 = blockIdx.x * 32, b0 = blockIdx.y * 32;
    int tx = threadIdx.x, ty = threadIdx.y;
#pragma unroll
    for (int j = 0; j < 32; j += 8)
        tile[ty + j][tx] = x[(size_t)(b0 + ty + j) * INDIM + i0 + tx];
    __syncthreads();
#pragma unroll
    for (int j = 0; j < 32; j += 8)
        g_xT[(size_t)(i0 + ty + j) * BDIM + b0 + tx] = tile[tx][ty + j];
}

__global__ void prep_wc_kernel(const float* __restrict__ freqs,
                               const float* __restrict__ phases,
                               const float* __restrict__ beta,
                               const float* __restrict__ lamb) {
    __shared__ float  sS[FDIM];
    __shared__ __half tile[64 * 64];
    const int i  = blockIdx.x;
    const int o0 = blockIdx.y * 64;
    const int t  = threadIdx.x;       // 256 threads
    if (t < FDIM) {
        float w = freqs[t], p = phases[t];
        float m   = expf(-0.5f * w * w) * sinf(p);
        float var = 0.5f - 0.5f * expf(-2.f * w * w) * cosf(2.f * p) - m * m;
        sS[t] = rsqrtf(EPSV + var);
    }
    __syncthreads();
    const int f  = t & 63;
    const int ob = t >> 6;
#pragma unroll
    for (int e = 0; e < 16; ++e) {
        int ol = ob + 4 * e;
        int o  = o0 + ol;
        float v = sS[f] * beta[f * ODIM + o] * lamb[(size_t)i * ODIM + o];
        tile[ol * 64 + f] = __float2half_rn(v);
    }
    __syncthreads();
    const uint32_t* tw = (const uint32_t*)tile;
#pragma unroll
    for (int e = 0; e < 8; ++e) {
        int w2  = t + 256 * e;
        int row = w2 >> 5, col = w2 & 31;
        ((uint32_t*)(g_Wc + (size_t)(o0 + row) * KDIM + (size_t)i * 64))[col] =
            tw[row * 32 + col];
    }
}

// ---------------------------------------------------------------------------
// fused GEMM, 3-stage pipeline, gen/MMA interleaved.
// CTA: M=128 x N=256, 256 threads = 8 warps (2M x 4N), warp tile 64x64.
// Stages: A[3] 16KB, B[3] 32KB. B loaded 2 chunks ahead (wait_group 1),
// A generated 2 chunks ahead, gen rows interleaved between MMA k-steps.
// ---------------------------------------------------------------------------
#define SA_ST(s) ((uint32_t)(s) * 16384u)
#define SB_ST(s) (49152u + (uint32_t)(s) * 32768u)
#define SMEM_DYN (147456 + 1024)

__global__ void __launch_bounds__(256, 1)
gemm_kernel(const float* __restrict__ freqs, const float* __restrict__ phases,
            float* __restrict__ out) {
    extern __shared__ char dynraw[];
    char* dyn = (char*)(((uintptr_t)dynraw + 1023) & ~(uintptr_t)1023);
    const uint32_t db = smem_u32(dyn);

    const int tid  = threadIdx.x;
    const int lane = tid & 31;
    const int wid  = tid >> 5;
    const int wm   = wid >> 2;   // 0..1
    const int wn   = wid & 3;    // 0..3
    const int m_base = blockIdx.y * 128;
    const int n_base = blockIdx.x * 256;

    // --- A-generation mapping: thread owns 8 fixed f's x 4 rows ------------
    const int fg    = tid & 7;
    const int rbase = tid >> 3;
    float wreg[8], preg[8];
#pragma unroll
    for (int j = 0; j < 8; ++j) {
        wreg[j] = __ldg(freqs + fg * 8 + j);
        preg[j] = __ldg(phases + fg * 8 + j);
    }
    const uint32_t gxm  = (uint32_t)(rbase & 7) << 4;
    const uint32_t gcol = ((uint32_t)fg * 16u) ^ gxm;
    const float* xsrc = g_xT + m_base + rbase;

    // --- B cp.async mapping: one o-row per thread, 8x16B -------------------
    const uint32_t cbase = (uint32_t)tid * 128u;
    const uint32_t cxm   = (uint32_t)(tid & 7) << 4;
    const __half* csrc = g_Wc + (size_t)(n_base + tid) * KDIM;

    // --- ldmatrix lane addressing ------------------------------------------
    const int arow = wm * 64 + (lane & 15);
    const uint32_t aoff = (uint32_t)arow * 128u;
    const uint32_t xmA  = (uint32_t)(arow & 7) << 4;
    const uint32_t kqa  = (uint32_t)(lane >> 4) * 16u;
    const int brow = wn * 64 + (lane & 7) + (lane >> 4) * 8;
    const uint32_t boff = (uint32_t)brow * 128u;
    const uint32_t xmB  = (uint32_t)(lane & 7) << 4;
    const uint32_t kqb  = (uint32_t)((lane >> 3) & 1) * 16u;

    float acc[4][8][4];
#pragma unroll
    for (int mi = 0; mi < 4; ++mi)
#pragma unroll
        for (int nj = 0; nj < 8; ++nj)
#pragma unroll
            for (int c = 0; c < 4; ++c) acc[mi][nj][c] = 0.f;

    // one row of A-gen (8 sins -> one 16B granule)
    auto gen_row = [&](int r, float xv, uint32_t st) {
        uint32_t h[4];
#pragma unroll
        for (int j = 0; j < 4; ++j) {
            float t0 = fmaf(wreg[2 * j],     xv, preg[2 * j]);
            float t1 = fmaf(wreg[2 * j + 1], xv, preg[2 * j + 1]);
            t0 = fmaf(-6.2831853f, rintf(t0 * 0.15915494f), t0);
            t1 = fmaf(-6.2831853f, rintf(t1 * 0.15915494f), t1);
            __half2 hh = __floats2half2_rn(__sinf(t0), __sinf(t1));
            h[j] = *(uint32_t*)&hh;
        }
        STS128(db + st + ((uint32_t)(rbase + 32 * r)) * 128u + gcol, h);
    };

    auto issue_b = [&](int kc, uint32_t st) {
        const char* s = (const char*)(csrc + (size_t)kc * 64);
#pragma unroll
        for (int j = 0; j < 8; ++j)
            CP_ASYNC16(db + st + cbase + (((uint32_t)(j * 16)) ^ cxm),
                       s + j * 16);
        asm volatile("cp.async.commit_group;" ::: "memory");
    };

    // --- prologue: B0,B1 in flight; A0,A1 generated ---
    issue_b(0, SB_ST(0));
    issue_b(1, SB_ST(1));
#pragma unroll
    for (int r = 0; r < 4; ++r) gen_row(r, xsrc[32 * r], SA_ST(0));
#pragma unroll
    for (int r = 0; r < 4; ++r) gen_row(r, xsrc[(size_t)BDIM + 32 * r], SA_ST(1));

#pragma unroll 1
    for (int kc = 0; kc < NKC; ++kc) {
        const int st  = kc % 3;
        const uint32_t sa = SA_ST(st);
        const uint32_t sb = SB_ST(st);

        if (kc + 1 < NKC)
            asm volatile("cp.async.wait_group 1;" ::: "memory");
        else
            asm volatile("cp.async.wait_group 0;" ::: "memory");
        __syncthreads();

        const bool do_gen = (kc + 2 < NKC);
        const int  nst    = (kc + 2) % 3;
        float xv[4];
        if (do_gen) {
            issue_b(kc + 2, SB_ST(nst));
            // prefetch x values for the chunk being generated (hides L2 lat)
#pragma unroll
            for (int r = 0; r < 4; ++r)
                xv[r] = xsrc[(size_t)(kc + 2) * BDIM + 32 * r];
        }

        // --- 4 k16 steps; A-gen row interleaved after each step ---
#pragma unroll
        for (int ks = 0; ks < 4; ++ks) {
            uint32_t a[4][4];
#pragma unroll
            for (int mi = 0; mi < 4; ++mi)
                LDSM4(a[mi], db + sa + aoff + (uint32_t)mi * 2048u +
                              (((uint32_t)(ks * 32) + kqa) ^ xmA));
            uint32_t b[4][4];
#pragma unroll
            for (int nq = 0; nq < 4; ++nq)
                LDSM4(b[nq], db + sb + boff + (uint32_t)nq * 2048u +
                              (((uint32_t)(ks * 32) + kqb) ^ xmB));
#pragma unroll
            for (int mi = 0; mi < 4; ++mi)
#pragma unroll
                for (int nj = 0; nj < 8; ++nj)
                    MMA16816(acc[mi][nj], a[mi],
                             b[nj >> 1][(nj & 1) * 2],
                             b[nj >> 1][(nj & 1) * 2 + 1]);
            if (do_gen)
                gen_row(ks, xv[ks], SA_ST(nst));  // MUFU/FMA/STS in HMMA shadow
        }
    }

    // --- epilogue: acc + bias -> out ---
#pragma unroll
    for (int mi = 0; mi < 4; ++mi) {
        int row = m_base + wm * 64 + mi * 16 + (lane >> 2);
        float* o0 = out + (size_t)row * ODIM + n_base;
        float* o1 = o0 + (size_t)8 * ODIM;
#pragma unroll
        for (int nj = 0; nj < 8; ++nj) {
            int cl = wn * 64 + nj * 8 + (lane & 3) * 2;
            float b0 = __ldg(g_biaseff + n_base + cl);
            float b1 = __ldg(g_biaseff + n_base + cl + 1);
            float2 v0 = make_float2(acc[mi][nj][0] + b0, acc[mi][nj][1] + b1);
            float2 v1 = make_float2(acc[mi][nj][2] + b0, acc[mi][nj][3] + b1);
            *(float2*)(o0 + cl) = v0;
            *(float2*)(o1 + cl) = v1;
        }
    }
}

// ---------------------------------------------------------------------------
extern "C" void kernel_launch(void* const* d_in, const int* in_sizes, int n_in,
                              void* d_out, int out_size) {
    (void)in_sizes; (void)n_in; (void)out_size;
    const float* x      = (const float*)d_in[0];
    const float* freqs  = (const float*)d_in[1];
    const float* phases = (const float*)d_in[2];
    const float* beta   = (const float*)d_in[3];
    const float* lamb   = (const float*)d_in[4];
    const float* bias   = (const float*)d_in[5];
    float* out = (float*)d_out;

    cudaFuncSetAttribute(gemm_kernel,
                         cudaFuncAttributeMaxDynamicSharedMemorySize, SMEM_DYN);

    prep_bias_kernel<<<(ODIM + 255) / 256, 256>>>(freqs, phases, beta, lamb, bias);
    prep_xT_kernel<<<dim3(INDIM / 32, BDIM / 32), dim3(32, 8)>>>(x);
    prep_wc_kernel<<<dim3(INDIM, ODIM / 64), 256>>>(freqs, phases, beta, lamb);
    gemm_kernel<<<dim3(ODIM / 256, BDIM / 128), 256, SMEM_DYN>>>(freqs, phases, out);
}